// round 10
// baseline (speedup 1.0000x reference)
#include <cuda_runtime.h>
#include <cuda_bf16.h>
#include <cstdint>
#include <cstddef>

typedef unsigned long long u64;
typedef unsigned int u32;
typedef unsigned short u16;

#define B_  64
#define T_  1024
#define D_  512
#define H_  768
#define G_  3072

// ---------------- static device scratch ----------------
__device__ float g_xz[(size_t)2 * T_ * G_ * B_];                 // [dir][t][col][b]
__device__ __align__(16) __nv_bfloat16 g_hbf[2][3][2][B_][H_];   // [dir][buf][hi/lo][b][k]
__device__ __align__(16) __nv_bfloat16 g_xs[(size_t)B_ * T_ * 1536];      // [m=t*64+b][xhi|xlo|xhi]
__device__ __align__(16) __nv_bfloat16 g_ws[(size_t)2 * 1536 * G_];       // [dir][Whi;Whi;Wlo][col]
__device__ unsigned g_cnt[2];
__device__ __align__(128) unsigned g_flag[2][64][32];            // per-CTA 128B flag lines

// ---------------- helpers ----------------
__device__ __forceinline__ unsigned ld_acq(const unsigned* p) {
    unsigned v; asm volatile("ld.acquire.gpu.b32 %0, [%1];" : "=r"(v) : "l"(p) : "memory"); return v;
}
__device__ __forceinline__ void red_rel_add1(unsigned* p) {
    asm volatile("red.release.gpu.add.u32 [%0], %1;" :: "l"(p), "r"(1u) : "memory");
}
__device__ __forceinline__ void st_rel(unsigned* p, unsigned v) {
    asm volatile("st.release.gpu.u32 [%0], %1;" :: "l"(p), "r"(v) : "memory");
}
__device__ __forceinline__ float sigf(float x) { return __fdividef(1.0f, 1.0f + __expf(-x)); }
__device__ __forceinline__ float tanh_(float x) { return 1.0f - __fdividef(2.0f, __expf(2.0f*x) + 1.0f); }
__device__ __forceinline__ u32 smem_u32(const void* p) {
    u32 a; asm("{ .reg .u64 t; cvta.to.shared.u64 t, %1; cvt.u32.u64 %0, t; }" : "=r"(a) : "l"(p)); return a;
}

#define LDSM4(r, a) \
    asm volatile("ldmatrix.sync.aligned.m8n8.x4.shared.b16 {%0,%1,%2,%3}, [%4];" \
        : "=r"((r)[0]),"=r"((r)[1]),"=r"((r)[2]),"=r"((r)[3]) : "r"(a))
#define LDSM4T(r, a) \
    asm volatile("ldmatrix.sync.aligned.m8n8.x4.trans.shared.b16 {%0,%1,%2,%3}, [%4];" \
        : "=r"((r)[0]),"=r"((r)[1]),"=r"((r)[2]),"=r"((r)[3]) : "r"(a))
#define MMA(d, a, b0, b1) \
    asm volatile("mma.sync.aligned.m16n8k16.row.col.f32.bf16.bf16.f32 " \
        "{%0,%1,%2,%3}, {%4,%5,%6,%7}, {%8,%9}, {%0,%1,%2,%3};" \
        : "+f"((d)[0]),"+f"((d)[1]),"+f"((d)[2]),"+f"((d)[3]) \
        : "r"((a)[0]),"r"((a)[1]),"r"((a)[2]),"r"((a)[3]), "r"(b0),"r"(b1))

__device__ __forceinline__ u32 pack2(__nv_bfloat16 a, __nv_bfloat16 b) {
    return (u32)__bfloat16_as_ushort(a) | ((u32)__bfloat16_as_ushort(b) << 16);
}

// =====================================================================
// pack_x: x[b][t][k] fp32 -> g_xs[m=t*64+b][ xhi(512) | xlo(512) | xhi(512) ] bf16
// =====================================================================
__global__ void __launch_bounds__(256) pack_x(const float* __restrict__ x)
{
    if (blockIdx.x == 0 && threadIdx.x < 130) {
        if (threadIdx.x < 2) g_cnt[threadIdx.x] = 0;
        else { int i = threadIdx.x - 2; g_flag[i >> 6][i & 63][0] = 0; }
    }
    size_t i4 = (size_t)blockIdx.x * 256 + threadIdx.x;
    size_t e  = i4 * 4;
    int b = (int)(e >> 19), t = (int)((e >> 9) & 1023), k = (int)(e & 511);
    float4 v = *reinterpret_cast<const float4*>(x + e);
    __nv_bfloat16 h0 = __float2bfloat16(v.x), h1 = __float2bfloat16(v.y);
    __nv_bfloat16 h2 = __float2bfloat16(v.z), h3 = __float2bfloat16(v.w);
    __nv_bfloat16 l0 = __float2bfloat16(v.x - __bfloat162float(h0));
    __nv_bfloat16 l1 = __float2bfloat16(v.y - __bfloat162float(h1));
    __nv_bfloat16 l2 = __float2bfloat16(v.z - __bfloat162float(h2));
    __nv_bfloat16 l3 = __float2bfloat16(v.w - __bfloat162float(h3));
    uint2 hp = make_uint2(pack2(h0, h1), pack2(h2, h3));
    uint2 lp = make_uint2(pack2(l0, l1), pack2(l2, l3));
    size_t m = (size_t)t * 64 + b;
    *reinterpret_cast<uint2*>(&g_xs[m * 1536 + k])        = hp;
    *reinterpret_cast<uint2*>(&g_xs[m * 1536 + 512 + k])  = lp;
    *reinterpret_cast<uint2*>(&g_xs[m * 1536 + 1024 + k]) = hp;
}

// =====================================================================
// pack_w: W[k][col] fp32 -> g_ws[dir][ Whi(512) ; Whi(512) ; Wlo(512) ][col] bf16
// =====================================================================
__global__ void __launch_bounds__(256) pack_w(const float* __restrict__ Wf,
                                              const float* __restrict__ Wb)
{
    size_t idx = (size_t)blockIdx.x * 256 + threadIdx.x;
    int dir = (int)(idx / 393216);
    size_t r = idx % 393216;
    int k = (int)(r / 768), c4 = (int)(r % 768) * 4;
    const float* W = dir ? Wb : Wf;
    float4 v = *reinterpret_cast<const float4*>(W + (size_t)k * G_ + c4);
    __nv_bfloat16 h0 = __float2bfloat16(v.x), h1 = __float2bfloat16(v.y);
    __nv_bfloat16 h2 = __float2bfloat16(v.z), h3 = __float2bfloat16(v.w);
    __nv_bfloat16 l0 = __float2bfloat16(v.x - __bfloat162float(h0));
    __nv_bfloat16 l1 = __float2bfloat16(v.y - __bfloat162float(h1));
    __nv_bfloat16 l2 = __float2bfloat16(v.z - __bfloat162float(h2));
    __nv_bfloat16 l3 = __float2bfloat16(v.w - __bfloat162float(h3));
    uint2 hp = make_uint2(pack2(h0, h1), pack2(h2, h3));
    uint2 lp = make_uint2(pack2(l0, l1), pack2(l2, l3));
    __nv_bfloat16* base = g_ws + (size_t)dir * 1536 * G_;
    *reinterpret_cast<uint2*>(&base[(size_t)k * G_ + c4])          = hp;
    *reinterpret_cast<uint2*>(&base[(size_t)(k + 512) * G_ + c4])  = hp;
    *reinterpret_cast<uint2*>(&base[(size_t)(k + 1024) * G_ + c4]) = lp;
}

// =====================================================================
// proj_mma (unchanged, known-good)
// =====================================================================
#define SA0 0
#define SA1 18432
#define SB0 36864
#define SB1 54272
#define PROJ_SMEM 71680

__device__ __forceinline__ void proj_cp(u32 sa, u32 sbuf, int my, int dir, int bx, int kb, int tid)
{
    const __nv_bfloat16* asrc = g_xs + (size_t)my * 128 * 1536 + kb * 64;
#pragma unroll
    for (int q = 0; q < 4; ++q) {
        int j = q * 256 + tid;
        int r = j >> 3, seg = j & 7;
        u32 d = sa + (u32)(r * 144 + seg * 16);
        const void* s = asrc + (size_t)r * 1536 + seg * 8;
        asm volatile("cp.async.cg.shared.global [%0], [%1], 16;" :: "r"(d), "l"(s) : "memory");
    }
    const __nv_bfloat16* bsrc = g_ws + ((size_t)dir * 1536 + kb * 64) * G_ + bx * 128;
#pragma unroll
    for (int q = 0; q < 4; ++q) {
        int j = q * 256 + tid;
        int k = j >> 4, seg = j & 15;
        u32 d = sbuf + (u32)(k * 272 + seg * 16);
        const void* s = bsrc + (size_t)k * G_ + seg * 8;
        asm volatile("cp.async.cg.shared.global [%0], [%1], 16;" :: "r"(d), "l"(s) : "memory");
    }
    asm volatile("cp.async.commit_group;" ::: "memory");
}

__global__ void __launch_bounds__(256, 2)
proj_mma(const float* __restrict__ bf, const float* __restrict__ bb)
{
    extern __shared__ char psm[];
    const u32 sb = smem_u32(psm);
    const int tid = threadIdx.x, w = tid >> 5, l = tid & 31;
    const int bx = blockIdx.x, my = blockIdx.y, dir = blockIdx.z;
    const float* bias = dir ? bb : bf;
    const int mrow0 = 32 * (w & 3), wn = w >> 2;

    const u32 aoff = (u32)((mrow0 + (l & 15)) * 144 + (l >> 4) * 16);
    const u32 boff = (u32)(((l & 7) + 8 * ((l >> 3) & 1)) * 272 + (l >> 4) * 16 + wn * 128);

    float acc[2][8][4];
#pragma unroll
    for (int m = 0; m < 2; ++m)
#pragma unroll
        for (int n = 0; n < 8; ++n)
#pragma unroll
            for (int e = 0; e < 4; ++e) acc[m][n][e] = 0.0f;

    float bv[8][2];
#pragma unroll
    for (int nt = 0; nt < 8; ++nt) {
        int c = bx * 128 + wn * 64 + nt * 8 + 2 * (l & 3);
        bv[nt][0] = bias[c]; bv[nt][1] = bias[c + 1];
    }

    proj_cp(sb + SA0, sb + SB0, my, dir, bx, 0, tid);
    for (int kb = 0; kb < 24; ++kb) {
        asm volatile("cp.async.wait_group 0;" ::: "memory");
        __syncthreads();
        if (kb + 1 < 24)
            proj_cp(sb + (((kb + 1) & 1) ? SA1 : SA0),
                    sb + (((kb + 1) & 1) ? SB1 : SB0), my, dir, bx, kb + 1, tid);
        const u32 uA = sb + ((kb & 1) ? SA1 : SA0) + aoff;
        const u32 uB = sb + ((kb & 1) ? SB1 : SB0) + boff;
#pragma unroll
        for (int ks = 0; ks < 4; ++ks) {
            u32 a0[4], a1[4];
            LDSM4(a0, uA + ks * 32);
            LDSM4(a1, uA + ks * 32 + 16 * 144);
#pragma unroll
            for (int j = 0; j < 4; ++j) {
                u32 bq[4];
                LDSM4T(bq, uB + ks * 16 * 272 + j * 32);
                MMA(acc[0][2*j],   a0, bq[0], bq[1]);
                MMA(acc[0][2*j+1], a0, bq[2], bq[3]);
                MMA(acc[1][2*j],   a1, bq[0], bq[1]);
                MMA(acc[1][2*j+1], a1, bq[2], bq[3]);
            }
        }
    }

#pragma unroll
    for (int mm = 0; mm < 2; ++mm)
#pragma unroll
        for (int p = 0; p < 2; ++p) {
            int m = (my << 7) + mrow0 + mm * 16 + p * 8 + (l >> 2);
            int t = m >> 6, b = m & 63;
            float* basep = g_xz +
                (((size_t)dir * T_ + t) * G_ + bx * 128 + wn * 64 + 2 * (l & 3)) * 64 + b;
#pragma unroll
            for (int nt = 0; nt < 8; ++nt) {
                basep[(size_t)nt * 512]      = acc[mm][nt][2*p]     + bv[nt][0];
                basep[(size_t)nt * 512 + 64] = acc[mm][nt][2*p + 1] + bv[nt][1];
            }
        }
}

// =====================================================================
// Kernel 2: persistent recurrence (R9 compute core; new 2-level barrier,
// out-writes moved off the release critical path).
// =====================================================================
#define BPITCH 208
#define APITCH 272
#define HA0_   159744
#define HA1_   194560
#define RNN_SMEM 229376

__device__ __forceinline__ void cp_chunk(u32 dst, const __nv_bfloat16* hsrc, int ch, int tid)
{
#pragma unroll
    for (int q = 0; q < 8; ++q) {
        int j = q * 256 + tid;
        int r = j >> 4, seg = j & 15;
        u32 d = dst + (u32)(r * APITCH + seg * 16);
        const void* src = hsrc + (size_t)r * H_ + ch * 128 + seg * 8;
        asm volatile("cp.async.cg.shared.global [%0], [%1], 16;" :: "r"(d), "l"(src) : "memory");
    }
    asm volatile("cp.async.commit_group;" ::: "memory");
}

__global__ void __launch_bounds__(256)
rnn_kernel(const float* __restrict__ Uf, const float* __restrict__ Ub, float* __restrict__ out)
{
    extern __shared__ char smem[];
    const u32 sb = smem_u32(smem);
    const int tid = threadIdx.x, w = tid >> 5, l = tid & 31;
    const int dir = blockIdx.x >> 6;
    const int lc  = blockIdx.x & 63;           // local CTA id within direction
    const int u0  = lc * 12;
    const float* U = dir ? Ub : Uf;

    for (int i = tid; i < 768 * 96; i += 256) {
        int k = i / 96, n = i - k * 96;
        int nn = (n < 48) ? n : n - 48;
        int g = nn / 12, uu = nn - g * 12;
        float v = U[(size_t)k * G_ + g * H_ + u0 + uu];
        __nv_bfloat16 hi = __float2bfloat16(v);
        __nv_bfloat16 val = (n < 48) ? hi : __float2bfloat16(v - __bfloat162float(hi));
        *reinterpret_cast<__nv_bfloat16*>(smem + k * BPITCH + n * 2) = val;
    }
    __syncthreads();

    float* zsm = reinterpret_cast<float*>(smem + HA0_);
    const int b = tid & 63, uh = tid >> 6;
    float cst[3] = {0, 0, 0};

    const u32 aoff = (u32)((16 * w + (l & 15)) * APITCH + (l >> 4) * 16);
    const u32 boff = (u32)(((l & 7) + 8 * ((l >> 3) & 1)) * BPITCH + (l >> 4) * 16);
    const int qd = w >> 2;

    for (int s = 0; s < T_; ++s) {
        const int tt = dir ? (T_ - 1 - s) : s;

        // xz prefetch first (no cross-CTA dependency)
        float xzv[12];
        const float* xzb = g_xz + (((size_t)dir * T_ + tt) * G_ + u0) * B_ + b;
#pragma unroll
        for (int g4 = 0; g4 < 4; ++g4)
#pragma unroll
            for (int j = 0; j < 3; ++j)
                xzv[g4 * 3 + j] = xzb[(size_t)(g4 * H_ + uh * 3 + j) * B_];

        if (s > 0) {
            // ---- two-level barrier: leader polls counter, fans out to flags ----
            if (lc == 0) {
                if (tid == 0) {
                    while (ld_acq(&g_cnt[dir]) < 64u * (u32)s) __nanosleep(64);
                }
                __syncthreads();
                if (tid >= 1 && tid < 64) st_rel(&g_flag[dir][tid][0], (u32)s);
            } else {
                if (tid == 0) {
                    while (ld_acq(&g_flag[dir][lc][0]) < (u32)s) {}
                }
                __syncthreads();
            }

            const __nv_bfloat16* hsrc = &g_hbf[dir][(s + 2) % 3][0][0][0];
            float acc[12][4];
#pragma unroll
            for (int n = 0; n < 12; ++n)
#pragma unroll
                for (int e = 0; e < 4; ++e) acc[n][e] = 0.0f;

            cp_chunk(sb + HA0_, hsrc, 0, tid);
            for (int ch = 0; ch < 6; ++ch) {
                asm volatile("cp.async.wait_group 0;" ::: "memory");
                __syncthreads();
                if (ch + 1 < 6) cp_chunk(sb + ((ch & 1) ? HA0_ : HA1_), hsrc, ch + 1, tid);

                const u32 aA  = sb + ((ch & 1) ? HA1_ : HA0_) + aoff;
                const u32 aB0 = sb + (u32)(ch * 128 * BPITCH) + boff;
#pragma unroll
                for (int ks = 0; ks < 8; ++ks) {
                    u32 a0[4];
                    LDSM4(a0, aA + ks * 32);
                    const u32 aBk = aB0 + ks * 16 * BPITCH;
#pragma unroll
                    for (int jp = 0; jp < 6; ++jp) {
                        u32 bq[4];
                        LDSM4T(bq, aBk + jp * 32);
                        MMA(acc[2*jp],   a0, bq[0], bq[1]);
                        MMA(acc[2*jp+1], a0, bq[2], bq[3]);
                    }
                }
            }
            __syncthreads();

            float* zq = zsm + qd * 3200;
            const int r0 = (w & 3) * 16 + (l >> 2);
#pragma unroll
            for (int j = 0; j < 6; ++j) {
                float z0 = acc[j][0] + acc[j+6][0];
                float z1 = acc[j][1] + acc[j+6][1];
                float z2 = acc[j][2] + acc[j+6][2];
                float z3 = acc[j][3] + acc[j+6][3];
                const int c = 8 * j + 2 * (l & 3);
                *reinterpret_cast<float2*>(&zq[r0 * 50 + c])       = make_float2(z0, z1);
                *reinterpret_cast<float2*>(&zq[(r0 + 8) * 50 + c]) = make_float2(z2, z3);
            }
            __syncthreads();
        }

        float hvv[3];
#pragma unroll
        for (int j = 0; j < 3; ++j) {
            const int u = uh * 3 + j;
            float zi = xzv[j], zf = xzv[3 + j], zg = xzv[6 + j], zo = xzv[9 + j];
            if (s > 0) {
                zi += zsm[b * 50 + u]      + zsm[3200 + b * 50 + u];
                zf += zsm[b * 50 + 12 + u] + zsm[3200 + b * 50 + 12 + u];
                zg += zsm[b * 50 + 24 + u] + zsm[3200 + b * 50 + 24 + u];
                zo += zsm[b * 50 + 36 + u] + zsm[3200 + b * 50 + 36 + u];
            }
            float iv = sigf(zi), fv = sigf(zf), gv = tanh_(zg), ov = sigf(zo);
            cst[j] = fv * cst[j] + iv * gv;
            float hv = ov * tanh_(cst[j]);
            hvv[j] = hv;
            __nv_bfloat16 hi = __float2bfloat16(hv);
            __nv_bfloat16 lo = __float2bfloat16(hv - __bfloat162float(hi));
            g_hbf[dir][s % 3][0][b][u0 + u] = hi;
            g_hbf[dir][s % 3][1][b][u0 + u] = lo;
        }
        __syncthreads();                       // all g_hbf writes issued
        if (tid == 0) red_rel_add1(&g_cnt[dir]);

        // big strided output writes OFF the release critical path
#pragma unroll
        for (int j = 0; j < 3; ++j) {
            const int u = uh * 3 + j;
            out[((size_t)b * T_ + tt) * (2 * H_) + dir * H_ + u0 + u] = hvv[j];
        }
    }
}

// =====================================================================
extern "C" void kernel_launch(void* const* d_in, const int* in_sizes, int n_in,
                              void* d_out, int out_size)
{
    const float* x  = (const float*)d_in[0];
    const float* Wf = (const float*)d_in[1];
    const float* Uf = (const float*)d_in[2];
    const float* bf = (const float*)d_in[3];
    const float* Wb = (const float*)d_in[4];
    const float* Ub = (const float*)d_in[5];
    const float* bb = (const float*)d_in[6];
    float* out = (float*)d_out;
    (void)in_sizes; (void)n_in; (void)out_size;

    cudaFuncSetAttribute(proj_mma, cudaFuncAttributeMaxDynamicSharedMemorySize, PROJ_SMEM);
    cudaFuncSetAttribute(rnn_kernel, cudaFuncAttributeMaxDynamicSharedMemorySize, RNN_SMEM);

    pack_x<<<32768, 256>>>(x);
    pack_w<<<3072, 256>>>(Wf, Wb);
    proj_mma<<<dim3(24, 512, 2), 256, PROJ_SMEM>>>(bf, bb);
    rnn_kernel<<<128, 256, RNN_SMEM>>>(Uf, Ub, out);
}

// round 11
// speedup vs baseline: 1.1956x; 1.1956x over previous
#include <cuda_runtime.h>
#include <cuda_bf16.h>
#include <cstdint>
#include <cstddef>

typedef unsigned long long u64;
typedef unsigned int u32;
typedef unsigned short u16;

#define B_  64
#define T_  1024
#define D_  512
#define H_  768
#define G_  3072

// ---------------- static device scratch ----------------
__device__ float g_xz[(size_t)2 * T_ * G_ * B_];                 // [dir][t][col][b]
__device__ __align__(16) __nv_bfloat16 g_hbf[2][3][2][B_][H_];   // [dir][buf][hi/lo][b][k]
__device__ __align__(16) __nv_bfloat16 g_xs[(size_t)B_ * T_ * 1536];      // [m=t*64+b][xhi|xlo|xhi]
__device__ __align__(16) __nv_bfloat16 g_ws[(size_t)2 * 1536 * G_];       // [dir][Whi;Whi;Wlo][col]
__device__ unsigned g_cnt[2];

// ---------------- helpers ----------------
__device__ __forceinline__ unsigned ld_acq(const unsigned* p) {
    unsigned v; asm volatile("ld.acquire.gpu.b32 %0, [%1];" : "=r"(v) : "l"(p) : "memory"); return v;
}
__device__ __forceinline__ void red_rel_add1(unsigned* p) {
    asm volatile("red.release.gpu.add.u32 [%0], %1;" :: "l"(p), "r"(1u) : "memory");
}
__device__ __forceinline__ float sigf(float x) { return __fdividef(1.0f, 1.0f + __expf(-x)); }
__device__ __forceinline__ float tanh_(float x) { return 1.0f - __fdividef(2.0f, __expf(2.0f*x) + 1.0f); }
__device__ __forceinline__ u32 smem_u32(const void* p) {
    u32 a; asm("{ .reg .u64 t; cvta.to.shared.u64 t, %1; cvt.u32.u64 %0, t; }" : "=r"(a) : "l"(p)); return a;
}

#define LDSM4(r, a) \
    asm volatile("ldmatrix.sync.aligned.m8n8.x4.shared.b16 {%0,%1,%2,%3}, [%4];" \
        : "=r"((r)[0]),"=r"((r)[1]),"=r"((r)[2]),"=r"((r)[3]) : "r"(a))
#define LDSM4T(r, a) \
    asm volatile("ldmatrix.sync.aligned.m8n8.x4.trans.shared.b16 {%0,%1,%2,%3}, [%4];" \
        : "=r"((r)[0]),"=r"((r)[1]),"=r"((r)[2]),"=r"((r)[3]) : "r"(a))
#define MMA(d, a, b0, b1) \
    asm volatile("mma.sync.aligned.m16n8k16.row.col.f32.bf16.bf16.f32 " \
        "{%0,%1,%2,%3}, {%4,%5,%6,%7}, {%8,%9}, {%0,%1,%2,%3};" \
        : "+f"((d)[0]),"+f"((d)[1]),"+f"((d)[2]),"+f"((d)[3]) \
        : "r"((a)[0]),"r"((a)[1]),"r"((a)[2]),"r"((a)[3]), "r"(b0),"r"(b1))

__device__ __forceinline__ u32 pack2(__nv_bfloat16 a, __nv_bfloat16 b) {
    return (u32)__bfloat16_as_ushort(a) | ((u32)__bfloat16_as_ushort(b) << 16);
}

// =====================================================================
// pack_x: x[b][t][k] fp32 -> g_xs[m=t*64+b][ xhi(512) | xlo(512) | xhi(512) ] bf16
// =====================================================================
__global__ void __launch_bounds__(256) pack_x(const float* __restrict__ x)
{
    if (blockIdx.x == 0 && threadIdx.x < 2) g_cnt[threadIdx.x] = 0;
    size_t i4 = (size_t)blockIdx.x * 256 + threadIdx.x;
    size_t e  = i4 * 4;
    int b = (int)(e >> 19), t = (int)((e >> 9) & 1023), k = (int)(e & 511);
    float4 v = *reinterpret_cast<const float4*>(x + e);
    __nv_bfloat16 h0 = __float2bfloat16(v.x), h1 = __float2bfloat16(v.y);
    __nv_bfloat16 h2 = __float2bfloat16(v.z), h3 = __float2bfloat16(v.w);
    __nv_bfloat16 l0 = __float2bfloat16(v.x - __bfloat162float(h0));
    __nv_bfloat16 l1 = __float2bfloat16(v.y - __bfloat162float(h1));
    __nv_bfloat16 l2 = __float2bfloat16(v.z - __bfloat162float(h2));
    __nv_bfloat16 l3 = __float2bfloat16(v.w - __bfloat162float(h3));
    uint2 hp = make_uint2(pack2(h0, h1), pack2(h2, h3));
    uint2 lp = make_uint2(pack2(l0, l1), pack2(l2, l3));
    size_t m = (size_t)t * 64 + b;
    *reinterpret_cast<uint2*>(&g_xs[m * 1536 + k])        = hp;
    *reinterpret_cast<uint2*>(&g_xs[m * 1536 + 512 + k])  = lp;
    *reinterpret_cast<uint2*>(&g_xs[m * 1536 + 1024 + k]) = hp;
}

// =====================================================================
// pack_w: W[k][col] fp32 -> g_ws[dir][ Whi(512) ; Whi(512) ; Wlo(512) ][col] bf16
// =====================================================================
__global__ void __launch_bounds__(256) pack_w(const float* __restrict__ Wf,
                                              const float* __restrict__ Wb)
{
    size_t idx = (size_t)blockIdx.x * 256 + threadIdx.x;
    int dir = (int)(idx / 393216);
    size_t r = idx % 393216;
    int k = (int)(r / 768), c4 = (int)(r % 768) * 4;
    const float* W = dir ? Wb : Wf;
    float4 v = *reinterpret_cast<const float4*>(W + (size_t)k * G_ + c4);
    __nv_bfloat16 h0 = __float2bfloat16(v.x), h1 = __float2bfloat16(v.y);
    __nv_bfloat16 h2 = __float2bfloat16(v.z), h3 = __float2bfloat16(v.w);
    __nv_bfloat16 l0 = __float2bfloat16(v.x - __bfloat162float(h0));
    __nv_bfloat16 l1 = __float2bfloat16(v.y - __bfloat162float(h1));
    __nv_bfloat16 l2 = __float2bfloat16(v.z - __bfloat162float(h2));
    __nv_bfloat16 l3 = __float2bfloat16(v.w - __bfloat162float(h3));
    uint2 hp = make_uint2(pack2(h0, h1), pack2(h2, h3));
    uint2 lp = make_uint2(pack2(l0, l1), pack2(l2, l3));
    __nv_bfloat16* base = g_ws + (size_t)dir * 1536 * G_;
    *reinterpret_cast<uint2*>(&base[(size_t)k * G_ + c4])          = hp;
    *reinterpret_cast<uint2*>(&base[(size_t)(k + 512) * G_ + c4])  = hp;
    *reinterpret_cast<uint2*>(&base[(size_t)(k + 1024) * G_ + c4]) = lp;
}

// =====================================================================
// proj_mma (unchanged, known-good)
// =====================================================================
#define SA0 0
#define SA1 18432
#define SB0 36864
#define SB1 54272
#define PROJ_SMEM 71680

__device__ __forceinline__ void proj_cp(u32 sa, u32 sbuf, int my, int dir, int bx, int kb, int tid)
{
    const __nv_bfloat16* asrc = g_xs + (size_t)my * 128 * 1536 + kb * 64;
#pragma unroll
    for (int q = 0; q < 4; ++q) {
        int j = q * 256 + tid;
        int r = j >> 3, seg = j & 7;
        u32 d = sa + (u32)(r * 144 + seg * 16);
        const void* s = asrc + (size_t)r * 1536 + seg * 8;
        asm volatile("cp.async.cg.shared.global [%0], [%1], 16;" :: "r"(d), "l"(s) : "memory");
    }
    const __nv_bfloat16* bsrc = g_ws + ((size_t)dir * 1536 + kb * 64) * G_ + bx * 128;
#pragma unroll
    for (int q = 0; q < 4; ++q) {
        int j = q * 256 + tid;
        int k = j >> 4, seg = j & 15;
        u32 d = sbuf + (u32)(k * 272 + seg * 16);
        const void* s = bsrc + (size_t)k * G_ + seg * 8;
        asm volatile("cp.async.cg.shared.global [%0], [%1], 16;" :: "r"(d), "l"(s) : "memory");
    }
    asm volatile("cp.async.commit_group;" ::: "memory");
}

__global__ void __launch_bounds__(256, 2)
proj_mma(const float* __restrict__ bf, const float* __restrict__ bb)
{
    extern __shared__ char psm[];
    const u32 sb = smem_u32(psm);
    const int tid = threadIdx.x, w = tid >> 5, l = tid & 31;
    const int bx = blockIdx.x, my = blockIdx.y, dir = blockIdx.z;
    const float* bias = dir ? bb : bf;
    const int mrow0 = 32 * (w & 3), wn = w >> 2;

    const u32 aoff = (u32)((mrow0 + (l & 15)) * 144 + (l >> 4) * 16);
    const u32 boff = (u32)(((l & 7) + 8 * ((l >> 3) & 1)) * 272 + (l >> 4) * 16 + wn * 128);

    float acc[2][8][4];
#pragma unroll
    for (int m = 0; m < 2; ++m)
#pragma unroll
        for (int n = 0; n < 8; ++n)
#pragma unroll
            for (int e = 0; e < 4; ++e) acc[m][n][e] = 0.0f;

    float bv[8][2];
#pragma unroll
    for (int nt = 0; nt < 8; ++nt) {
        int c = bx * 128 + wn * 64 + nt * 8 + 2 * (l & 3);
        bv[nt][0] = bias[c]; bv[nt][1] = bias[c + 1];
    }

    proj_cp(sb + SA0, sb + SB0, my, dir, bx, 0, tid);
    for (int kb = 0; kb < 24; ++kb) {
        asm volatile("cp.async.wait_group 0;" ::: "memory");
        __syncthreads();
        if (kb + 1 < 24)
            proj_cp(sb + (((kb + 1) & 1) ? SA1 : SA0),
                    sb + (((kb + 1) & 1) ? SB1 : SB0), my, dir, bx, kb + 1, tid);
        const u32 uA = sb + ((kb & 1) ? SA1 : SA0) + aoff;
        const u32 uB = sb + ((kb & 1) ? SB1 : SB0) + boff;
#pragma unroll
        for (int ks = 0; ks < 4; ++ks) {
            u32 a0[4], a1[4];
            LDSM4(a0, uA + ks * 32);
            LDSM4(a1, uA + ks * 32 + 16 * 144);
#pragma unroll
            for (int j = 0; j < 4; ++j) {
                u32 bq[4];
                LDSM4T(bq, uB + ks * 16 * 272 + j * 32);
                MMA(acc[0][2*j],   a0, bq[0], bq[1]);
                MMA(acc[0][2*j+1], a0, bq[2], bq[3]);
                MMA(acc[1][2*j],   a1, bq[0], bq[1]);
                MMA(acc[1][2*j+1], a1, bq[2], bq[3]);
            }
        }
    }

#pragma unroll
    for (int mm = 0; mm < 2; ++mm)
#pragma unroll
        for (int p = 0; p < 2; ++p) {
            int m = (my << 7) + mrow0 + mm * 16 + p * 8 + (l >> 2);
            int t = m >> 6, b = m & 63;
            float* basep = g_xz +
                (((size_t)dir * T_ + t) * G_ + bx * 128 + wn * 64 + 2 * (l & 3)) * 64 + b;
#pragma unroll
            for (int nt = 0; nt < 8; ++nt) {
                basep[(size_t)nt * 512]      = acc[mm][nt][2*p]     + bv[nt][0];
                basep[(size_t)nt * 512 + 64] = acc[mm][nt][2*p + 1] + bv[nt][1];
            }
        }
}

// =====================================================================
// Kernel 2: persistent recurrence (R9 core + single-counter barrier +
// staged COALESCED h publish: 3x8B stores per (plane,b) instead of
// 12 scattered 2B stores -> short drain before red.release).
// =====================================================================
#define BPITCH 208
#define APITCH 272
#define HA0_   159744
#define HA1_   194560
#define RNN_SMEM 229376

__device__ __forceinline__ void cp_chunk(u32 dst, const __nv_bfloat16* hsrc, int ch, int tid)
{
#pragma unroll
    for (int q = 0; q < 8; ++q) {
        int j = q * 256 + tid;
        int r = j >> 4, seg = j & 15;
        u32 d = dst + (u32)(r * APITCH + seg * 16);
        const void* src = hsrc + (size_t)r * H_ + ch * 128 + seg * 8;
        asm volatile("cp.async.cg.shared.global [%0], [%1], 16;" :: "r"(d), "l"(src) : "memory");
    }
    asm volatile("cp.async.commit_group;" ::: "memory");
}

__global__ void __launch_bounds__(256)
rnn_kernel(const float* __restrict__ Uf, const float* __restrict__ Ub, float* __restrict__ out)
{
    extern __shared__ char smem[];
    const u32 sb = smem_u32(smem);
    const int tid = threadIdx.x, w = tid >> 5, l = tid & 31;
    const int dir = blockIdx.x >> 6;
    const int u0  = (blockIdx.x & 63) * 12;
    const float* U = dir ? Ub : Uf;

    for (int i = tid; i < 768 * 96; i += 256) {
        int k = i / 96, n = i - k * 96;
        int nn = (n < 48) ? n : n - 48;
        int g = nn / 12, uu = nn - g * 12;
        float v = U[(size_t)k * G_ + g * H_ + u0 + uu];
        __nv_bfloat16 hi = __float2bfloat16(v);
        __nv_bfloat16 val = (n < 48) ? hi : __float2bfloat16(v - __bfloat162float(hi));
        *reinterpret_cast<__nv_bfloat16*>(smem + k * BPITCH + n * 2) = val;
    }
    __syncthreads();

    float* zsm = reinterpret_cast<float*>(smem + HA0_);            // [2][64][50] floats
    __nv_bfloat16* hstg = reinterpret_cast<__nv_bfloat16*>(zsm + 6400);  // [2][64][12] bf16
    const int b = tid & 63, uh = tid >> 6;
    float cst[3] = {0, 0, 0};

    const u32 aoff = (u32)((16 * w + (l & 15)) * APITCH + (l >> 4) * 16);
    const u32 boff = (u32)(((l & 7) + 8 * ((l >> 3) & 1)) * BPITCH + (l >> 4) * 16);
    const int qd = w >> 2;

    for (int s = 0; s < T_; ++s) {
        const int tt = dir ? (T_ - 1 - s) : s;

        // xz prefetch first (no cross-CTA dependency; hides barrier wait)
        float xzv[12];
        const float* xzb = g_xz + (((size_t)dir * T_ + tt) * G_ + u0) * B_ + b;
#pragma unroll
        for (int g4 = 0; g4 < 4; ++g4)
#pragma unroll
            for (int j = 0; j < 3; ++j)
                xzv[g4 * 3 + j] = xzb[(size_t)(g4 * H_ + uh * 3 + j) * B_];

        if (s > 0) {
            if (tid == 0) { while (ld_acq(&g_cnt[dir]) < 64u * (u32)s) {} }
            __syncthreads();

            const __nv_bfloat16* hsrc = &g_hbf[dir][(s + 2) % 3][0][0][0];
            float acc[12][4];
#pragma unroll
            for (int n = 0; n < 12; ++n)
#pragma unroll
                for (int e = 0; e < 4; ++e) acc[n][e] = 0.0f;

            cp_chunk(sb + HA0_, hsrc, 0, tid);
            for (int ch = 0; ch < 6; ++ch) {
                asm volatile("cp.async.wait_group 0;" ::: "memory");
                __syncthreads();
                if (ch + 1 < 6) cp_chunk(sb + ((ch & 1) ? HA0_ : HA1_), hsrc, ch + 1, tid);

                const u32 aA  = sb + ((ch & 1) ? HA1_ : HA0_) + aoff;
                const u32 aB0 = sb + (u32)(ch * 128 * BPITCH) + boff;
#pragma unroll
                for (int ks = 0; ks < 8; ++ks) {
                    u32 a0[4];
                    LDSM4(a0, aA + ks * 32);
                    const u32 aBk = aB0 + ks * 16 * BPITCH;
#pragma unroll
                    for (int jp = 0; jp < 6; ++jp) {
                        u32 bq[4];
                        LDSM4T(bq, aBk + jp * 32);
                        MMA(acc[2*jp],   a0, bq[0], bq[1]);
                        MMA(acc[2*jp+1], a0, bq[2], bq[3]);
                    }
                }
            }
            __syncthreads();

            float* zq = zsm + qd * 3200;
            const int r0 = (w & 3) * 16 + (l >> 2);
#pragma unroll
            for (int j = 0; j < 6; ++j) {
                float z0 = acc[j][0] + acc[j+6][0];
                float z1 = acc[j][1] + acc[j+6][1];
                float z2 = acc[j][2] + acc[j+6][2];
                float z3 = acc[j][3] + acc[j+6][3];
                const int c = 8 * j + 2 * (l & 3);
                *reinterpret_cast<float2*>(&zq[r0 * 50 + c])       = make_float2(z0, z1);
                *reinterpret_cast<float2*>(&zq[(r0 + 8) * 50 + c]) = make_float2(z2, z3);
            }
            __syncthreads();
        }

        float hvv[3];
#pragma unroll
        for (int j = 0; j < 3; ++j) {
            const int u = uh * 3 + j;
            float zi = xzv[j], zf = xzv[3 + j], zg = xzv[6 + j], zo = xzv[9 + j];
            if (s > 0) {
                zi += zsm[b * 50 + u]      + zsm[3200 + b * 50 + u];
                zf += zsm[b * 50 + 12 + u] + zsm[3200 + b * 50 + 12 + u];
                zg += zsm[b * 50 + 24 + u] + zsm[3200 + b * 50 + 24 + u];
                zo += zsm[b * 50 + 36 + u] + zsm[3200 + b * 50 + 36 + u];
            }
            float iv = sigf(zi), fv = sigf(zf), gv = tanh_(zg), ov = sigf(zo);
            cst[j] = fv * cst[j] + iv * gv;
            float hv = ov * tanh_(cst[j]);
            hvv[j] = hv;
            __nv_bfloat16 hi = __float2bfloat16(hv);
            __nv_bfloat16 lo = __float2bfloat16(hv - __bfloat162float(hi));
            hstg[(0 * 64 + b) * 12 + u] = hi;   // stage in smem (transpose)
            hstg[(1 * 64 + b) * 12 + u] = lo;
        }
        __syncthreads();                        // staging complete

        // coalesced publish: 384 aligned 8B stores (vs 1536 scattered 2B)
        {
            __nv_bfloat16* hdst = &g_hbf[dir][s % 3][0][0][u0];
#pragma unroll
            for (int i = tid; i < 384; i += 256) {
                int pair = i / 3, part = i - pair * 3;        // pair = plane*64+b
                u64 v = *reinterpret_cast<const u64*>(&hstg[pair * 12 + part * 4]);
                *reinterpret_cast<u64*>(&hdst[(size_t)pair * H_ + part * 4]) = v;
            }
        }
        __syncthreads();                        // publish stores issued
        if (tid == 0) red_rel_add1(&g_cnt[dir]);

        // big strided output writes off the release critical path
#pragma unroll
        for (int j = 0; j < 3; ++j) {
            const int u = uh * 3 + j;
            out[((size_t)b * T_ + tt) * (2 * H_) + dir * H_ + u0 + u] = hvv[j];
        }
    }
}

// =====================================================================
extern "C" void kernel_launch(void* const* d_in, const int* in_sizes, int n_in,
                              void* d_out, int out_size)
{
    const float* x  = (const float*)d_in[0];
    const float* Wf = (const float*)d_in[1];
    const float* Uf = (const float*)d_in[2];
    const float* bf = (const float*)d_in[3];
    const float* Wb = (const float*)d_in[4];
    const float* Ub = (const float*)d_in[5];
    const float* bb = (const float*)d_in[6];
    float* out = (float*)d_out;
    (void)in_sizes; (void)n_in; (void)out_size;

    cudaFuncSetAttribute(proj_mma, cudaFuncAttributeMaxDynamicSharedMemorySize, PROJ_SMEM);
    cudaFuncSetAttribute(rnn_kernel, cudaFuncAttributeMaxDynamicSharedMemorySize, RNN_SMEM);

    pack_x<<<32768, 256>>>(x);
    pack_w<<<3072, 256>>>(Wf, Wb);
    proj_mma<<<dim3(24, 512, 2), 256, PROJ_SMEM>>>(bf, bb);
    rnn_kernel<<<128, 256, RNN_SMEM>>>(Uf, Ub, out);
}

// round 12
// speedup vs baseline: 1.2587x; 1.0528x over previous
#include <cuda_runtime.h>
#include <cuda_bf16.h>
#include <cstdint>
#include <cstddef>

typedef unsigned long long u64;
typedef unsigned int u32;
typedef unsigned short u16;

#define B_  64
#define T_  1024
#define D_  512
#define H_  768
#define G_  3072

// ---------------- static device scratch ----------------
__device__ float g_xz[(size_t)2 * T_ * G_ * B_];                 // [dir][t][col][b]
__device__ __align__(16) __nv_bfloat16 g_hbf[2][3][2][B_][H_];   // [dir][buf][hi/lo][b][k]
__device__ __align__(16) __nv_bfloat16 g_xs[(size_t)B_ * T_ * 1536];      // [m=t*64+b][xhi|xlo|xhi]
__device__ __align__(16) __nv_bfloat16 g_ws[(size_t)2 * 1536 * G_];       // [dir][Whi;Whi;Wlo][col]
__device__ unsigned g_cnt[2];

// ---------------- helpers ----------------
__device__ __forceinline__ unsigned ld_acq(const unsigned* p) {
    unsigned v; asm volatile("ld.acquire.gpu.b32 %0, [%1];" : "=r"(v) : "l"(p) : "memory"); return v;
}
__device__ __forceinline__ void red_rel_add1(unsigned* p) {
    asm volatile("red.release.gpu.add.u32 [%0], %1;" :: "l"(p), "r"(1u) : "memory");
}
__device__ __forceinline__ float sigf(float x) { return __fdividef(1.0f, 1.0f + __expf(-x)); }
__device__ __forceinline__ float tanh_(float x) { return 1.0f - __fdividef(2.0f, __expf(2.0f*x) + 1.0f); }
__device__ __forceinline__ u32 smem_u32(const void* p) {
    u32 a; asm("{ .reg .u64 t; cvta.to.shared.u64 t, %1; cvt.u32.u64 %0, t; }" : "=r"(a) : "l"(p)); return a;
}

#define LDSM4(r, a) \
    asm volatile("ldmatrix.sync.aligned.m8n8.x4.shared.b16 {%0,%1,%2,%3}, [%4];" \
        : "=r"((r)[0]),"=r"((r)[1]),"=r"((r)[2]),"=r"((r)[3]) : "r"(a))
#define LDSM4T(r, a) \
    asm volatile("ldmatrix.sync.aligned.m8n8.x4.trans.shared.b16 {%0,%1,%2,%3}, [%4];" \
        : "=r"((r)[0]),"=r"((r)[1]),"=r"((r)[2]),"=r"((r)[3]) : "r"(a))
#define MMA(d, a, b0, b1) \
    asm volatile("mma.sync.aligned.m16n8k16.row.col.f32.bf16.bf16.f32 " \
        "{%0,%1,%2,%3}, {%4,%5,%6,%7}, {%8,%9}, {%0,%1,%2,%3};" \
        : "+f"((d)[0]),"+f"((d)[1]),"+f"((d)[2]),"+f"((d)[3]) \
        : "r"((a)[0]),"r"((a)[1]),"r"((a)[2]),"r"((a)[3]), "r"(b0),"r"(b1))

__device__ __forceinline__ u32 pack2(__nv_bfloat16 a, __nv_bfloat16 b) {
    return (u32)__bfloat16_as_ushort(a) | ((u32)__bfloat16_as_ushort(b) << 16);
}

// =====================================================================
// pack_x: x[b][t][k] fp32 -> g_xs[m=t*64+b][ xhi(512) | xlo(512) | xhi(512) ] bf16
// =====================================================================
__global__ void __launch_bounds__(256) pack_x(const float* __restrict__ x)
{
    if (blockIdx.x == 0 && threadIdx.x < 2) g_cnt[threadIdx.x] = 0;
    size_t i4 = (size_t)blockIdx.x * 256 + threadIdx.x;
    size_t e  = i4 * 4;
    int b = (int)(e >> 19), t = (int)((e >> 9) & 1023), k = (int)(e & 511);
    float4 v = *reinterpret_cast<const float4*>(x + e);
    __nv_bfloat16 h0 = __float2bfloat16(v.x), h1 = __float2bfloat16(v.y);
    __nv_bfloat16 h2 = __float2bfloat16(v.z), h3 = __float2bfloat16(v.w);
    __nv_bfloat16 l0 = __float2bfloat16(v.x - __bfloat162float(h0));
    __nv_bfloat16 l1 = __float2bfloat16(v.y - __bfloat162float(h1));
    __nv_bfloat16 l2 = __float2bfloat16(v.z - __bfloat162float(h2));
    __nv_bfloat16 l3 = __float2bfloat16(v.w - __bfloat162float(h3));
    uint2 hp = make_uint2(pack2(h0, h1), pack2(h2, h3));
    uint2 lp = make_uint2(pack2(l0, l1), pack2(l2, l3));
    size_t m = (size_t)t * 64 + b;
    *reinterpret_cast<uint2*>(&g_xs[m * 1536 + k])        = hp;
    *reinterpret_cast<uint2*>(&g_xs[m * 1536 + 512 + k])  = lp;
    *reinterpret_cast<uint2*>(&g_xs[m * 1536 + 1024 + k]) = hp;
}

// =====================================================================
// pack_w: W[k][col] fp32 -> g_ws[dir][ Whi(512) ; Whi(512) ; Wlo(512) ][col] bf16
// =====================================================================
__global__ void __launch_bounds__(256) pack_w(const float* __restrict__ Wf,
                                              const float* __restrict__ Wb)
{
    size_t idx = (size_t)blockIdx.x * 256 + threadIdx.x;
    int dir = (int)(idx / 393216);
    size_t r = idx % 393216;
    int k = (int)(r / 768), c4 = (int)(r % 768) * 4;
    const float* W = dir ? Wb : Wf;
    float4 v = *reinterpret_cast<const float4*>(W + (size_t)k * G_ + c4);
    __nv_bfloat16 h0 = __float2bfloat16(v.x), h1 = __float2bfloat16(v.y);
    __nv_bfloat16 h2 = __float2bfloat16(v.z), h3 = __float2bfloat16(v.w);
    __nv_bfloat16 l0 = __float2bfloat16(v.x - __bfloat162float(h0));
    __nv_bfloat16 l1 = __float2bfloat16(v.y - __bfloat162float(h1));
    __nv_bfloat16 l2 = __float2bfloat16(v.z - __bfloat162float(h2));
    __nv_bfloat16 l3 = __float2bfloat16(v.w - __bfloat162float(h3));
    uint2 hp = make_uint2(pack2(h0, h1), pack2(h2, h3));
    uint2 lp = make_uint2(pack2(l0, l1), pack2(l2, l3));
    __nv_bfloat16* base = g_ws + (size_t)dir * 1536 * G_;
    *reinterpret_cast<uint2*>(&base[(size_t)k * G_ + c4])          = hp;
    *reinterpret_cast<uint2*>(&base[(size_t)(k + 512) * G_ + c4])  = hp;
    *reinterpret_cast<uint2*>(&base[(size_t)(k + 1024) * G_ + c4]) = lp;
}

// =====================================================================
// proj_mma (unchanged, known-good)
// =====================================================================
#define SA0 0
#define SA1 18432
#define SB0 36864
#define SB1 54272
#define PROJ_SMEM 71680

__device__ __forceinline__ void proj_cp(u32 sa, u32 sbuf, int my, int dir, int bx, int kb, int tid)
{
    const __nv_bfloat16* asrc = g_xs + (size_t)my * 128 * 1536 + kb * 64;
#pragma unroll
    for (int q = 0; q < 4; ++q) {
        int j = q * 256 + tid;
        int r = j >> 3, seg = j & 7;
        u32 d = sa + (u32)(r * 144 + seg * 16);
        const void* s = asrc + (size_t)r * 1536 + seg * 8;
        asm volatile("cp.async.cg.shared.global [%0], [%1], 16;" :: "r"(d), "l"(s) : "memory");
    }
    const __nv_bfloat16* bsrc = g_ws + ((size_t)dir * 1536 + kb * 64) * G_ + bx * 128;
#pragma unroll
    for (int q = 0; q < 4; ++q) {
        int j = q * 256 + tid;
        int k = j >> 4, seg = j & 15;
        u32 d = sbuf + (u32)(k * 272 + seg * 16);
        const void* s = bsrc + (size_t)k * G_ + seg * 8;
        asm volatile("cp.async.cg.shared.global [%0], [%1], 16;" :: "r"(d), "l"(s) : "memory");
    }
    asm volatile("cp.async.commit_group;" ::: "memory");
}

__global__ void __launch_bounds__(256, 2)
proj_mma(const float* __restrict__ bf, const float* __restrict__ bb)
{
    extern __shared__ char psm[];
    const u32 sb = smem_u32(psm);
    const int tid = threadIdx.x, w = tid >> 5, l = tid & 31;
    const int bx = blockIdx.x, my = blockIdx.y, dir = blockIdx.z;
    const float* bias = dir ? bb : bf;
    const int mrow0 = 32 * (w & 3), wn = w >> 2;

    const u32 aoff = (u32)((mrow0 + (l & 15)) * 144 + (l >> 4) * 16);
    const u32 boff = (u32)(((l & 7) + 8 * ((l >> 3) & 1)) * 272 + (l >> 4) * 16 + wn * 128);

    float acc[2][8][4];
#pragma unroll
    for (int m = 0; m < 2; ++m)
#pragma unroll
        for (int n = 0; n < 8; ++n)
#pragma unroll
            for (int e = 0; e < 4; ++e) acc[m][n][e] = 0.0f;

    float bv[8][2];
#pragma unroll
    for (int nt = 0; nt < 8; ++nt) {
        int c = bx * 128 + wn * 64 + nt * 8 + 2 * (l & 3);
        bv[nt][0] = bias[c]; bv[nt][1] = bias[c + 1];
    }

    proj_cp(sb + SA0, sb + SB0, my, dir, bx, 0, tid);
    for (int kb = 0; kb < 24; ++kb) {
        asm volatile("cp.async.wait_group 0;" ::: "memory");
        __syncthreads();
        if (kb + 1 < 24)
            proj_cp(sb + (((kb + 1) & 1) ? SA1 : SA0),
                    sb + (((kb + 1) & 1) ? SB1 : SB0), my, dir, bx, kb + 1, tid);
        const u32 uA = sb + ((kb & 1) ? SA1 : SA0) + aoff;
        const u32 uB = sb + ((kb & 1) ? SB1 : SB0) + boff;
#pragma unroll
        for (int ks = 0; ks < 4; ++ks) {
            u32 a0[4], a1[4];
            LDSM4(a0, uA + ks * 32);
            LDSM4(a1, uA + ks * 32 + 16 * 144);
#pragma unroll
            for (int j = 0; j < 4; ++j) {
                u32 bq[4];
                LDSM4T(bq, uB + ks * 16 * 272 + j * 32);
                MMA(acc[0][2*j],   a0, bq[0], bq[1]);
                MMA(acc[0][2*j+1], a0, bq[2], bq[3]);
                MMA(acc[1][2*j],   a1, bq[0], bq[1]);
                MMA(acc[1][2*j+1], a1, bq[2], bq[3]);
            }
        }
    }

#pragma unroll
    for (int mm = 0; mm < 2; ++mm)
#pragma unroll
        for (int p = 0; p < 2; ++p) {
            int m = (my << 7) + mrow0 + mm * 16 + p * 8 + (l >> 2);
            int t = m >> 6, b = m & 63;
            float* basep = g_xz +
                (((size_t)dir * T_ + t) * G_ + bx * 128 + wn * 64 + 2 * (l & 3)) * 64 + b;
#pragma unroll
            for (int nt = 0; nt < 8; ++nt) {
                basep[(size_t)nt * 512]      = acc[mm][nt][2*p]     + bv[nt][0];
                basep[(size_t)nt * 512 + 64] = acc[mm][nt][2*p + 1] + bv[nt][1];
            }
        }
}

// =====================================================================
// Kernel 2: persistent recurrence. R11 skeleton; warp grid 4(M)x2(N),
// lo*Ulo quadrant dropped (2^-18), 3-plane fold in smem.
// =====================================================================
#define BPITCH 208
#define APITCH 272
#define HA0_   159744
#define HA1_   194560
#define RNN_SMEM 229376

__device__ __forceinline__ void cp_chunk(u32 dst, const __nv_bfloat16* hsrc, int ch, int tid)
{
#pragma unroll
    for (int q = 0; q < 8; ++q) {
        int j = q * 256 + tid;
        int r = j >> 4, seg = j & 15;
        u32 d = dst + (u32)(r * APITCH + seg * 16);
        const void* src = hsrc + (size_t)r * H_ + ch * 128 + seg * 8;
        asm volatile("cp.async.cg.shared.global [%0], [%1], 16;" :: "r"(d), "l"(src) : "memory");
    }
    asm volatile("cp.async.commit_group;" ::: "memory");
}

__global__ void __launch_bounds__(256)
rnn_kernel(const float* __restrict__ Uf, const float* __restrict__ Ub, float* __restrict__ out)
{
    extern __shared__ char smem[];
    const u32 sb = smem_u32(smem);
    const int tid = threadIdx.x, w = tid >> 5, l = tid & 31;
    const int dir = blockIdx.x >> 6;
    const int u0  = (blockIdx.x & 63) * 12;
    const float* U = dir ? Ub : Uf;

    for (int i = tid; i < 768 * 96; i += 256) {
        int k = i / 96, n = i - k * 96;
        int nn = (n < 48) ? n : n - 48;
        int g = nn / 12, uu = nn - g * 12;
        float v = U[(size_t)k * G_ + g * H_ + u0 + uu];
        __nv_bfloat16 hi = __float2bfloat16(v);
        __nv_bfloat16 val = (n < 48) ? hi : __float2bfloat16(v - __bfloat162float(hi));
        *reinterpret_cast<__nv_bfloat16*>(smem + k * BPITCH + n * 2) = val;
    }
    __syncthreads();

    float* zsm = reinterpret_cast<float*>(smem + HA0_);            // [3][64][50] floats
    __nv_bfloat16* hstg = reinterpret_cast<__nv_bfloat16*>(zsm + 9600); // [2][64][12] bf16
    const int b = tid & 63, uh = tid >> 6;
    float cst[3] = {0, 0, 0};

    // warp grid: mg = M group (32 rows), ng = N group (48 cols)
    const int mg = w & 3, ng = w >> 2;
    const bool active = (ng == 0) || (mg < 2);        // drop lo*Ulo quadrant
    const int plane = ng ? 1 : ((mg >> 1) ? 2 : 0);   // 0:hi*Uhi 1:hi*Ulo 2:lo*Uhi

    const u32 aoff = (u32)((32 * mg + (l & 15)) * APITCH + (l >> 4) * 16);
    const u32 boff = (u32)(((l & 7) + 8 * ((l >> 3) & 1)) * BPITCH + (l >> 4) * 16 + ng * 96);

    for (int s = 0; s < T_; ++s) {
        const int tt = dir ? (T_ - 1 - s) : s;

        // xz prefetch first (no cross-CTA dependency; hides barrier wait)
        float xzv[12];
        const float* xzb = g_xz + (((size_t)dir * T_ + tt) * G_ + u0) * B_ + b;
#pragma unroll
        for (int g4 = 0; g4 < 4; ++g4)
#pragma unroll
            for (int j = 0; j < 3; ++j)
                xzv[g4 * 3 + j] = xzb[(size_t)(g4 * H_ + uh * 3 + j) * B_];

        if (s > 0) {
            if (tid == 0) { while (ld_acq(&g_cnt[dir]) < 64u * (u32)s) {} }
            __syncthreads();

            const __nv_bfloat16* hsrc = &g_hbf[dir][(s + 2) % 3][0][0][0];
            float acc[12][4];
#pragma unroll
            for (int n = 0; n < 12; ++n)
#pragma unroll
                for (int e = 0; e < 4; ++e) acc[n][e] = 0.0f;

            cp_chunk(sb + HA0_, hsrc, 0, tid);
            for (int ch = 0; ch < 6; ++ch) {
                asm volatile("cp.async.wait_group 0;" ::: "memory");
                __syncthreads();
                if (ch + 1 < 6) cp_chunk(sb + ((ch & 1) ? HA0_ : HA1_), hsrc, ch + 1, tid);

                if (active) {
                    const u32 aA  = sb + ((ch & 1) ? HA1_ : HA0_) + aoff;
                    const u32 aB0 = sb + (u32)(ch * 128 * BPITCH) + boff;
#pragma unroll
                    for (int ks = 0; ks < 8; ++ks) {
                        u32 a0[4], a1[4];
                        LDSM4(a0, aA + ks * 32);
                        LDSM4(a1, aA + ks * 32 + 16 * APITCH);
                        const u32 aBk = aB0 + ks * 16 * BPITCH;
#pragma unroll
                        for (int jj = 0; jj < 3; ++jj) {
                            u32 bq[4];
                            LDSM4T(bq, aBk + jj * 32);
                            MMA(acc[2*jj],     a0, bq[0], bq[1]);
                            MMA(acc[2*jj+1],   a0, bq[2], bq[3]);
                            MMA(acc[6+2*jj],   a1, bq[0], bq[1]);
                            MMA(acc[6+2*jj+1], a1, bq[2], bq[3]);
                        }
                    }
                }
            }
            __syncthreads();   // buffer reads done before zsm (alias) writes

            if (active) {
                float* zq = zsm + plane * 3200;
#pragma unroll
                for (int m = 0; m < 2; ++m) {
                    const int r = (mg & 1) * 32 + m * 16 + (l >> 2);
#pragma unroll
                    for (int n2 = 0; n2 < 6; ++n2) {
                        const int c = n2 * 8 + 2 * (l & 3);
                        *reinterpret_cast<float2*>(&zq[r * 50 + c]) =
                            make_float2(acc[m*6+n2][0], acc[m*6+n2][1]);
                        *reinterpret_cast<float2*>(&zq[(r + 8) * 50 + c]) =
                            make_float2(acc[m*6+n2][2], acc[m*6+n2][3]);
                    }
                }
            }
            __syncthreads();
        }

        float hvv[3];
#pragma unroll
        for (int j = 0; j < 3; ++j) {
            const int u = uh * 3 + j;
            float zi = xzv[j], zf = xzv[3 + j], zg = xzv[6 + j], zo = xzv[9 + j];
            if (s > 0) {
                zi += zsm[b*50 + u]        + zsm[3200 + b*50 + u]        + zsm[6400 + b*50 + u];
                zf += zsm[b*50 + 12 + u]   + zsm[3200 + b*50 + 12 + u]   + zsm[6400 + b*50 + 12 + u];
                zg += zsm[b*50 + 24 + u]   + zsm[3200 + b*50 + 24 + u]   + zsm[6400 + b*50 + 24 + u];
                zo += zsm[b*50 + 36 + u]   + zsm[3200 + b*50 + 36 + u]   + zsm[6400 + b*50 + 36 + u];
            }
            float iv = sigf(zi), fv = sigf(zf), gv = tanh_(zg), ov = sigf(zo);
            cst[j] = fv * cst[j] + iv * gv;
            float hv = ov * tanh_(cst[j]);
            hvv[j] = hv;
            __nv_bfloat16 hi = __float2bfloat16(hv);
            __nv_bfloat16 lo = __float2bfloat16(hv - __bfloat162float(hi));
            hstg[(0 * 64 + b) * 12 + u] = hi;
            hstg[(1 * 64 + b) * 12 + u] = lo;
        }
        __syncthreads();

        // coalesced publish: 384 aligned 8B stores
        {
            __nv_bfloat16* hdst = &g_hbf[dir][s % 3][0][0][u0];
#pragma unroll
            for (int i = tid; i < 384; i += 256) {
                int pair = i / 3, part = i - pair * 3;
                u64 v = *reinterpret_cast<const u64*>(&hstg[pair * 12 + part * 4]);
                *reinterpret_cast<u64*>(&hdst[(size_t)pair * H_ + part * 4]) = v;
            }
        }
        __syncthreads();
        if (tid == 0) red_rel_add1(&g_cnt[dir]);

        // strided output writes off the release critical path
#pragma unroll
        for (int j = 0; j < 3; ++j) {
            const int u = uh * 3 + j;
            out[((size_t)b * T_ + tt) * (2 * H_) + dir * H_ + u0 + u] = hvv[j];
        }
    }
}

// =====================================================================
extern "C" void kernel_launch(void* const* d_in, const int* in_sizes, int n_in,
                              void* d_out, int out_size)
{
    const float* x  = (const float*)d_in[0];
    const float* Wf = (const float*)d_in[1];
    const float* Uf = (const float*)d_in[2];
    const float* bf = (const float*)d_in[3];
    const float* Wb = (const float*)d_in[4];
    const float* Ub = (const float*)d_in[5];
    const float* bb = (const float*)d_in[6];
    float* out = (float*)d_out;
    (void)in_sizes; (void)n_in; (void)out_size;

    cudaFuncSetAttribute(proj_mma, cudaFuncAttributeMaxDynamicSharedMemorySize, PROJ_SMEM);
    cudaFuncSetAttribute(rnn_kernel, cudaFuncAttributeMaxDynamicSharedMemorySize, RNN_SMEM);

    pack_x<<<32768, 256>>>(x);
    pack_w<<<3072, 256>>>(Wf, Wb);
    proj_mma<<<dim3(24, 512, 2), 256, PROJ_SMEM>>>(bf, bb);
    rnn_kernel<<<128, 256, RNN_SMEM>>>(Uf, Ub, out);
}